// round 5
// baseline (speedup 1.0000x reference)
#include <cuda_runtime.h>
#include <cstdint>

#define FS 8
#define T_STEPS 101
#define DT_F 20.0f
#define TWO_PI_F 6.28318530717958647692f
#define INV_TWO_PI_F 0.15915494309189533577f

// ---- drift lookup table: quadratic per-cell coefficients ----
// Range [-8, 8), 512 cells, cell width exactly 1/32 (exact fp32 index math).
#define LUT_N 512
#define LUT_XMIN (-8.0f)
#define LUT_DX 0.03125f            // 1/32
#define LUT_INV_DX 32.0f
#define LUT_OFF 256.0f             // -XMIN * INV_DX

__device__ float4 g_lut[LUT_N];

// drift(x) * DT, evaluated directly (only used in tiny LUT builder)
__device__ __forceinline__ float drift_dt(float x,
                                          const float* __restrict__ sw,
                                          const float* __restrict__ cw) {
    float acc = cw[0];               // f=0: sin=0, cos=1
    #pragma unroll
    for (int f = 1; f < FS; f++) {
        float s, c;
        sincosf((float)f * x, &s, &c);
        acc = fmaf(s, sw[f], acc);
        acc = fmaf(c, cw[f], acc);
    }
    return acc * DT_F;
}

__global__ void build_lut_kernel(const float* __restrict__ sw,
                                 const float* __restrict__ cw) {
    int i = blockIdx.x * blockDim.x + threadIdx.x;
    if (i >= LUT_N) return;
    float xn = LUT_XMIN + (float)i * LUT_DX;
    float f0 = drift_dt(xn, sw, cw);
    float fm = drift_dt(xn + 0.5f * LUT_DX, sw, cw);
    float f1 = drift_dt(xn + LUT_DX, sw, cw);
    // quadratic through (0,f0),(0.5,fm),(1,f1), local u in [0,1]
    float c2 = 2.0f * (f0 - 2.0f * fm + f1);
    float c1 = -3.0f * f0 + 4.0f * fm - f1;
    g_lut[i] = make_float4(f0, c1, c2, 0.0f);
}

// ---- main integration kernel ----
#define WARPS_PER_BLOCK 4

__global__ void __launch_bounds__(128, 12)
drifter_main(const float* __restrict__ x0,
             float* __restrict__ out,
             int B) {
    __shared__ float4 lut[LUT_N];                       // 8 KB
    __shared__ float tile[WARPS_PER_BLOCK][32][17];     // 8.7 KB

    for (int i = threadIdx.x; i < LUT_N; i += 128)
        lut[i] = g_lut[i];
    __syncthreads();

    const int lane = threadIdx.x & 31;
    const int warp = threadIdx.x >> 5;
    const int b0 = (blockIdx.x * WARPS_PER_BLOCK + warp) * 32;

    float x = x0[b0 + lane];

    float (*sh)[17] = tile[warp];
    const size_t half = (size_t)B * T_STEPS;

    // flush mapping: lanes 0-15 -> row pair base 0, lanes 16-31 -> +1
    const int fcol = lane & 15;
    const int frow = lane >> 4;

    int t0 = 0;
    #pragma unroll 1
    for (int tile_i = 0; tile_i < 6; tile_i++, t0 += 16) {
        #pragma unroll
        for (int j = 0; j < 16; j++) {
            // wrap to [-pi, pi): x - 2pi*round(x/2pi)
            sh[lane][j] = fmaf(-TWO_PI_F, rintf(x * INV_TWO_PI_F), x);

            // Euler step via quadratic LUT interpolation
            float tp = fmaf(x, LUT_INV_DX, LUT_OFF);
            float fi = floorf(tp);
            int idx = (int)fi;
            idx = max(0, min(idx, LUT_N - 1));
            float u = tp - fi;
            float4 e = lut[idx];
            x += fmaf(u, fmaf(u, e.z, e.y), e.x);
        }
        __syncwarp();

        // flush: 2 rows per iteration, 16 consecutive cols per row
        float tmv = (float)(t0 + fcol) * DT_F;
        size_t off = (size_t)(b0 + frow) * T_STEPS + (t0 + fcol);
        #pragma unroll
        for (int i = 0; i < 32; i += 2) {
            float v = sh[i + frow][fcol];
            out[off]        = tmv;
            out[half + off] = v;
            off += 2 * T_STEPS;
        }
        __syncwarp();
    }

    // tail: t = 96..100 (5 columns), advance x only 4 more times
    #pragma unroll
    for (int j = 0; j < 5; j++) {
        sh[lane][j] = fmaf(-TWO_PI_F, rintf(x * INV_TWO_PI_F), x);
        if (j < 4) {
            float tp = fmaf(x, LUT_INV_DX, LUT_OFF);
            float fi = floorf(tp);
            int idx = (int)fi;
            idx = max(0, min(idx, LUT_N - 1));
            float u = tp - fi;
            float4 e = lut[idx];
            x += fmaf(u, fmaf(u, e.z, e.y), e.x);
        }
    }
    __syncwarp();
    if (fcol < 5) {
        float tmv = (float)(96 + fcol) * DT_F;
        size_t off = (size_t)(b0 + frow) * T_STEPS + (96 + fcol);
        #pragma unroll
        for (int i = 0; i < 32; i += 2) {
            float v = sh[i + frow][fcol];
            out[off]        = tmv;
            out[half + off] = v;
            off += 2 * T_STEPS;
        }
    }
}

extern "C" void kernel_launch(void* const* d_in, const int* in_sizes, int n_in,
                              void* d_out, int out_size) {
    const float* x0 = (const float*)d_in[0];   // x0_sample [B]
    const float* sw = (const float*)d_in[1];   // sin_weight [8]
    const float* cw = (const float*)d_in[2];   // cos_weight [8]
    // d_in[3] = t_sample: unused (doesn't affect reference output)
    float* out = (float*)d_out;

    const int B = in_sizes[0];

    build_lut_kernel<<<(LUT_N + 255) / 256, 256>>>(sw, cw);

    const int blocks = B / (WARPS_PER_BLOCK * 32);
    drifter_main<<<blocks, WARPS_PER_BLOCK * 32>>>(x0, out, B);
}

// round 6
// speedup vs baseline: 1.0008x; 1.0008x over previous
#include <cuda_runtime.h>
#include <cstdint>

#define FS 8
#define T_STEPS 101
#define DT_F 20.0f
#define TWO_PI_F 6.28318530717958647692f
#define INV_TWO_PI_F 0.15915494309189533577f

// ---- drift lookup table: quadratic per-cell coefficients ----
// Range [-8, 8), 512 cells, cell width exactly 1/32 (exact fp32 index math).
#define LUT_N 512
#define LUT_XMIN (-8.0f)
#define LUT_DX 0.03125f            // 1/32
#define LUT_INV_DX 32.0f
#define LUT_OFF 256.0f             // -XMIN * INV_DX

__device__ float4 g_lut[LUT_N];

// drift(x) * DT, evaluated directly (only used in tiny LUT builder)
__device__ __forceinline__ float drift_dt(float x,
                                          const float* __restrict__ sw,
                                          const float* __restrict__ cw) {
    float acc = cw[0];               // f=0: sin=0, cos=1
    #pragma unroll
    for (int f = 1; f < FS; f++) {
        float s, c;
        sincosf((float)f * x, &s, &c);
        acc = fmaf(s, sw[f], acc);
        acc = fmaf(c, cw[f], acc);
    }
    return acc * DT_F;
}

__global__ void build_lut_kernel(const float* __restrict__ sw,
                                 const float* __restrict__ cw) {
    int i = blockIdx.x * blockDim.x + threadIdx.x;
    if (i >= LUT_N) return;
    float xn = LUT_XMIN + (float)i * LUT_DX;
    float f0 = drift_dt(xn, sw, cw);
    float fm = drift_dt(xn + 0.5f * LUT_DX, sw, cw);
    float f1 = drift_dt(xn + LUT_DX, sw, cw);
    // quadratic through (0,f0),(0.5,fm),(1,f1), local u in [0,1]
    float c2 = 2.0f * (f0 - 2.0f * fm + f1);
    float c1 = -3.0f * f0 + 4.0f * fm - f1;
    g_lut[i] = make_float4(f0, c1, c2, 0.0f);
}

// ---- main integration kernel ----
#define WARPS_PER_BLOCK 4

__global__ void __launch_bounds__(128, 12)
drifter_main(const float* __restrict__ x0,
             float* __restrict__ out,
             int B) {
    __shared__ float4 lut[LUT_N];                       // 8 KB
    __shared__ float tile[WARPS_PER_BLOCK][32][17];     // 8.7 KB

    for (int i = threadIdx.x; i < LUT_N; i += 128)
        lut[i] = g_lut[i];
    __syncthreads();

    const int lane = threadIdx.x & 31;
    const int warp = threadIdx.x >> 5;
    const int b0 = (blockIdx.x * WARPS_PER_BLOCK + warp) * 32;

    float x = x0[b0 + lane];

    float (*sh)[17] = tile[warp];
    const size_t half = (size_t)B * T_STEPS;

    // flush mapping: lanes 0-15 -> row pair base 0, lanes 16-31 -> +1
    const int fcol = lane & 15;
    const int frow = lane >> 4;

    int t0 = 0;
    #pragma unroll 1
    for (int tile_i = 0; tile_i < 6; tile_i++, t0 += 16) {
        #pragma unroll
        for (int j = 0; j < 16; j++) {
            // wrap to [-pi, pi): x - 2pi*round(x/2pi)
            sh[lane][j] = fmaf(-TWO_PI_F, rintf(x * INV_TWO_PI_F), x);

            // Euler step via quadratic LUT interpolation
            float tp = fmaf(x, LUT_INV_DX, LUT_OFF);
            float fi = floorf(tp);
            int idx = (int)fi;
            idx = max(0, min(idx, LUT_N - 1));
            float u = tp - fi;
            float4 e = lut[idx];
            x += fmaf(u, fmaf(u, e.z, e.y), e.x);
        }
        __syncwarp();

        // flush: 2 rows per iteration, 16 consecutive cols per row
        float tmv = (float)(t0 + fcol) * DT_F;
        size_t off = (size_t)(b0 + frow) * T_STEPS + (t0 + fcol);
        #pragma unroll
        for (int i = 0; i < 32; i += 2) {
            float v = sh[i + frow][fcol];
            out[off]        = tmv;
            out[half + off] = v;
            off += 2 * T_STEPS;
        }
        __syncwarp();
    }

    // tail: t = 96..100 (5 columns), advance x only 4 more times
    #pragma unroll
    for (int j = 0; j < 5; j++) {
        sh[lane][j] = fmaf(-TWO_PI_F, rintf(x * INV_TWO_PI_F), x);
        if (j < 4) {
            float tp = fmaf(x, LUT_INV_DX, LUT_OFF);
            float fi = floorf(tp);
            int idx = (int)fi;
            idx = max(0, min(idx, LUT_N - 1));
            float u = tp - fi;
            float4 e = lut[idx];
            x += fmaf(u, fmaf(u, e.z, e.y), e.x);
        }
    }
    __syncwarp();
    if (fcol < 5) {
        float tmv = (float)(96 + fcol) * DT_F;
        size_t off = (size_t)(b0 + frow) * T_STEPS + (96 + fcol);
        #pragma unroll
        for (int i = 0; i < 32; i += 2) {
            float v = sh[i + frow][fcol];
            out[off]        = tmv;
            out[half + off] = v;
            off += 2 * T_STEPS;
        }
    }
}

extern "C" void kernel_launch(void* const* d_in, const int* in_sizes, int n_in,
                              void* d_out, int out_size) {
    const float* x0 = (const float*)d_in[0];   // x0_sample [B]
    const float* sw = (const float*)d_in[1];   // sin_weight [8]
    const float* cw = (const float*)d_in[2];   // cos_weight [8]
    // d_in[3] = t_sample: unused (doesn't affect reference output)
    float* out = (float*)d_out;

    const int B = in_sizes[0];

    build_lut_kernel<<<(LUT_N + 255) / 256, 256>>>(sw, cw);

    const int blocks = B / (WARPS_PER_BLOCK * 32);
    drifter_main<<<blocks, WARPS_PER_BLOCK * 32>>>(x0, out, B);
}

// round 7
// speedup vs baseline: 1.9506x; 1.9492x over previous
#include <cuda_runtime.h>
#include <cstdint>

#define FS 8
#define T_STEPS 101
#define DT_F 20.0f
#define TWO_PI_F 6.28318530717958647692f
#define INV_TWO_PI_F 0.15915494309189533577f

// ---- drift lookup table: quadratic per-cell coefficients ----
// Range [-8, 8), 512 cells, cell width exactly 1/32 (exact fp32 index math).
#define LUT_N 512
#define LUT_XMIN (-8.0f)
#define LUT_DX 0.03125f
#define LUT_INV_DX 32.0f
#define LUT_OFF 256.0f

__device__ float4 g_lut[LUT_N];

__device__ __forceinline__ float drift_dt(float x,
                                          const float* __restrict__ sw,
                                          const float* __restrict__ cw) {
    float acc = cw[0];
    #pragma unroll
    for (int f = 1; f < FS; f++) {
        float s, c;
        sincosf((float)f * x, &s, &c);
        acc = fmaf(s, sw[f], acc);
        acc = fmaf(c, cw[f], acc);
    }
    return acc * DT_F;
}

__global__ void build_lut_kernel(const float* __restrict__ sw,
                                 const float* __restrict__ cw) {
    int i = blockIdx.x * blockDim.x + threadIdx.x;
    if (i >= LUT_N) return;
    float xn = LUT_XMIN + (float)i * LUT_DX;
    float f0 = drift_dt(xn, sw, cw);
    float fm = drift_dt(xn + 0.5f * LUT_DX, sw, cw);
    float f1 = drift_dt(xn + LUT_DX, sw, cw);
    float c2 = 2.0f * (f0 - 2.0f * fm + f1);
    float c1 = -3.0f * f0 + 4.0f * fm - f1;
    g_lut[i] = make_float4(f0, c1, c2, 0.0f);
}

// ---- main integration kernel ----
// Each warp owns 32 consecutive trajectories (one per lane). The full
// [32][101] trajectory tile is buffered in dynamic shared memory, then each
// row (404 B) is flushed to global in ONE contiguous sweep so every 32B
// sector is fully written before eviction (no DRAM read-modify-write).
#define WARPS_PER_BLOCK 4
#define ROW_F 105                      // row stride in floats (odd-ish: 105%32=9, gcd=1)

extern __shared__ float smem_dyn[];

__global__ void __launch_bounds__(WARPS_PER_BLOCK * 32)
drifter_main(const float* __restrict__ x0,
             float* __restrict__ out,
             int B) {
    float4* lut = (float4*)smem_dyn;                 // 512 * 16 B = 8 KB
    float*  tiles = smem_dyn + LUT_N * 4;            // 4 * 32 * 105 floats

    const int tid  = threadIdx.x;
    for (int i = tid; i < LUT_N; i += WARPS_PER_BLOCK * 32)
        lut[i] = g_lut[i];
    __syncthreads();

    const int lane = tid & 31;
    const int warp = tid >> 5;
    const int b0 = (blockIdx.x * WARPS_PER_BLOCK + warp) * 32;

    float* tw = tiles + warp * (32 * ROW_F);         // this warp's tile
    float* trow = tw + lane * ROW_F;                 // this lane's row

    float x = x0[b0 + lane];

    // integrate: 101 outputs, 100 steps
    #pragma unroll 4
    for (int j = 0; j < T_STEPS; j++) {
        trow[j] = fmaf(-TWO_PI_F, rintf(x * INV_TWO_PI_F), x);
        if (j < T_STEPS - 1) {
            float tp = fmaf(x, LUT_INV_DX, LUT_OFF);
            float fi = floorf(tp);
            int idx = (int)fi;
            idx = max(0, min(idx, LUT_N - 1));
            float u = tp - fi;
            float4 e = lut[idx];
            x += fmaf(u, fmaf(u, e.z, e.y), e.x);
        }
    }
    __syncwarp();

    // flush: per row, one contiguous 404-B sweep (4 warp-wide STG bursts)
    const size_t half = (size_t)B * T_STEPS;
    const float tmv0 = (float)lane * DT_F;           // t_mesh for col=lane
    #pragma unroll 1
    for (int r = 0; r < 32; r++) {
        float* srow = tw + r * ROW_F;
        size_t rbase = (size_t)(b0 + r) * T_STEPS;
        #pragma unroll
        for (int k = 0; k < 4; k++) {
            int col = k * 32 + lane;
            if (col < T_STEPS) {
                float v = srow[col];
                out[rbase + col]        = fmaf((float)(k * 32), DT_F, tmv0);
                out[half + rbase + col] = v;
            }
        }
    }
}

extern "C" void kernel_launch(void* const* d_in, const int* in_sizes, int n_in,
                              void* d_out, int out_size) {
    const float* x0 = (const float*)d_in[0];
    const float* sw = (const float*)d_in[1];
    const float* cw = (const float*)d_in[2];
    // d_in[3] = t_sample: unused (doesn't affect reference output)
    float* out = (float*)d_out;

    const int B = in_sizes[0];

    build_lut_kernel<<<(LUT_N + 255) / 256, 256>>>(sw, cw);

    const int smem_bytes = LUT_N * 16 + WARPS_PER_BLOCK * 32 * ROW_F * 4; // 61952
    cudaFuncSetAttribute(drifter_main,
                         cudaFuncAttributeMaxDynamicSharedMemorySize, smem_bytes);

    const int blocks = B / (WARPS_PER_BLOCK * 32);
    drifter_main<<<blocks, WARPS_PER_BLOCK * 32, smem_bytes>>>(x0, out, B);
}